// round 4
// baseline (speedup 1.0000x reference)
#include <cuda_runtime.h>
#include <math.h>

#define NN 50000
#define EE 800000
#define CC 32
#define ZZ 10
#define LL 2
#define NB 8
#define HH 64
#define INV_AVG (1.0f/16.0f)
#define RCUT_INV (1.0f/5.0f)

typedef unsigned long long u64;

// ---------------- scratch (static device globals; no allocation) -------------
__device__ float g_s [NN*CC];
__device__ float g_v [NN*CC*3];
__device__ float g_su[NN*CC];
__device__ float g_vu[NN*CC*3];
__device__ float g_S [NN*CC];
__device__ float g_V [NN*CC*3];
__device__ float g_Y1[EE*3];
__device__ float g_ef[EE*NB];
__device__ int   g_z [NN];

// ---------------- packed fp32x2 helpers (SASS FFMA2 via PTX) -----------------
__device__ __forceinline__ u64 pack2(float lo, float hi) {
    u64 r; asm("mov.b64 %0, {%1,%2};" : "=l"(r) : "f"(lo), "f"(hi)); return r;
}
__device__ __forceinline__ float2 unpk(u64 v) {
    float2 f; asm("mov.b64 {%0,%1}, %2;" : "=f"(f.x), "=f"(f.y) : "l"(v)); return f;
}
__device__ __forceinline__ void ffma2(u64 &d, u64 a, u64 b) {
    asm("fma.rn.f32x2 %0, %1, %2, %0;" : "+l"(d) : "l"(a), "l"(b));
}
__device__ __forceinline__ float silu(float x) {
    return __fdividef(x, 1.0f + __expf(-x));
}

// ---------------- species index from one-hot ---------------------------------
__global__ void k_zidx(const float* __restrict__ attrs) {
    int n = blockIdx.x * blockDim.x + threadIdx.x;
    if (n >= NN) return;
    int z = 0;
#pragma unroll
    for (int j = 0; j < ZZ; j++)
        if (attrs[n*ZZ + j] > 0.5f) z = j;
    g_z[n] = z;
}

// ---------------- s = onehot @ W_embed, v = 0 --------------------------------
__global__ void k_embed(const float* __restrict__ W_embed) {
    int idx = blockIdx.x * blockDim.x + threadIdx.x;
    if (idx >= NN*CC) return;
    int n = idx >> 5, c = idx & 31;
    g_s[idx] = W_embed[g_z[n]*CC + c];
    g_v[idx*3 + 0] = 0.f;
    g_v[idx*3 + 1] = 0.f;
    g_v[idx*3 + 2] = 0.f;
}

// ---------------- edge geometry: Y1 + radial features ------------------------
__global__ void k_geom(const float* __restrict__ pos,
                       const float* __restrict__ shifts,
                       const int* __restrict__ src,
                       const int* __restrict__ dst) {
    int e = blockIdx.x * blockDim.x + threadIdx.x;
    if (e >= EE) return;
    int si = src[e], di = dst[e];
    float vx = pos[di*3+0] - pos[si*3+0] + shifts[e*3+0];
    float vy = pos[di*3+1] - pos[si*3+1] + shifts[e*3+1];
    float vz = pos[di*3+2] - pos[si*3+2] + shifts[e*3+2];
    float r  = sqrtf(vx*vx + vy*vy + vz*vz);
    float rs = fmaxf(r, 1e-9f);
    float inv = 1.0f / rs;
    g_Y1[e*3+0] = vx*inv;
    g_Y1[e*3+1] = vy*inv;
    g_Y1[e*3+2] = vz*inv;
    float x = r * RCUT_INV;
    float fc = 0.f;
    if (x < 1.0f) {
        float x2 = x*x, x3 = x2*x;
        float x6 = x3*x3, x7 = x6*x, x8 = x7*x;
        fc = 1.0f - 28.0f*x6 + 48.0f*x7 - 21.0f*x8;   // P=6 polynomial cutoff
    }
    float coef = 0.6324555320336759f * fc * inv;       // sqrt(2/RCUT)*fc/rs
    float arg0 = rs * (float)M_PI * RCUT_INV;
#pragma unroll
    for (int nb = 0; nb < NB; nb++)
        g_ef[e*NB + nb] = coef * sinf((float)(nb+1) * arg0);
}

// ---------------- node "up" linears: su = s@Wus, vu = v@Wuv ------------------
#define NWU 16
__global__ void k_nodeup(const float* __restrict__ Wus,
                         const float* __restrict__ Wuv) {
    __shared__ float sWs[CC*CC], sWv[CC*CC];
    __shared__ float st[NWU][128];
    int tid = threadIdx.x;
    for (int i = tid; i < CC*CC; i += blockDim.x) { sWs[i] = Wus[i]; sWv[i] = Wuv[i]; }
    __syncthreads();
    int warp = tid >> 5, lane = tid & 31;
    int n = blockIdx.x * NWU + warp;
    if (n >= NN) return;
    float* xs = st[warp];
    float* xv = st[warp] + 32;
    int b = (n*CC + lane)*3;
    xs[lane]       = g_s[n*CC + lane];
    xv[lane*3 + 0] = g_v[b+0];
    xv[lane*3 + 1] = g_v[b+1];
    xv[lane*3 + 2] = g_v[b+2];
    __syncwarp();
    float a = 0.f, u0 = 0.f, u1 = 0.f, u2 = 0.f;
#pragma unroll
    for (int k = 0; k < CC; k++) {
        float ws = sWs[k*CC + lane], wv = sWv[k*CC + lane];
        a  += xs[k]     * ws;
        u0 += xv[k*3+0] * wv;
        u1 += xv[k*3+1] * wv;
        u2 += xv[k*3+2] * wv;
    }
    g_su[n*CC + lane] = a;
    g_vu[b+0] = u0; g_vu[b+1] = u1; g_vu[b+2] = u2;
}

// ---------------- zero accumulators ------------------------------------------
__global__ void k_zero() {
    int i = blockIdx.x * blockDim.x + threadIdx.x;
    if (i < NN*CC)   g_S[i] = 0.f;
    if (i < NN*CC*3) g_V[i] = 0.f;
}

// ---------------- fused edge kernel ------------------------------------------
// Phase A (lane = edge): radial MLP stages 1-2 with broadcast LDS.128 weights
//   and FFMA2 packed math; silu'd hidden written transposed to per-warp smem.
// Phase B (lane = channel): stage-3 [64 -> 5x32] register-blocked over 8-edge
//   sub-batches (f32x2 over edge pairs), then TP message + atomic scatter.
#define EW 6
#define ETPB (EW*32)
#define HWF 2048   // 64*32 floats per warp

__global__ void __launch_bounds__(ETPB, 2)
k_edge(const float* __restrict__ R1,
       const float* __restrict__ R2,
       const float* __restrict__ R3,
       const int*  __restrict__ src,
       const int*  __restrict__ dst) {
    extern __shared__ float smf[];
    float* sR1  = smf;                      // 512
    float* sR2  = sR1 + NB*HH;              // 4096
    float* sR3  = sR2 + HH*HH;              // 10240
    float* hall = sR3 + HH*5*CC;            // EW*2048
    int tid = threadIdx.x;
    for (int i = tid; i < NB*HH;   i += ETPB) sR1[i] = R1[i];
    for (int i = tid; i < HH*HH;   i += ETPB) sR2[i] = R2[i];
    for (int i = tid; i < HH*5*CC; i += ETPB) sR3[i] = R3[i];
    __syncthreads();

    int warp = tid >> 5, lane = tid & 31;
    float* hw = hall + warp*HWF;
    const int nbatch = EE/32;   // 25000, exact

    for (int b = blockIdx.x*EW + warp; b < nbatch; b += gridDim.x*EW) {
        int ebase = b*32;
        int e = ebase + lane;

        // ======== phase A: lane = edge ========
        float4 efa = *(const float4*)&g_ef[e*NB];
        float4 efb = *(const float4*)&g_ef[e*NB + 4];
        float ef[8] = {efa.x, efa.y, efa.z, efa.w, efb.x, efb.y, efb.z, efb.w};

        // stage 1: [8] -> [64]
        u64 h2[32];
#pragma unroll
        for (int m = 0; m < 32; m++) h2[m] = 0ull;
#pragma unroll
        for (int k = 0; k < 8; k++) {
            u64 a = pack2(ef[k], ef[k]);
            const ulonglong2* row = (const ulonglong2*)(sR1 + k*HH);
#pragma unroll
            for (int m = 0; m < 16; m++) {
                ulonglong2 w = row[m];
                ffma2(h2[2*m],   a, w.x);
                ffma2(h2[2*m+1], a, w.y);
            }
        }
#pragma unroll
        for (int m = 0; m < 32; m++) {
            float2 f = unpk(h2[m]);
            h2[m] = pack2(silu(f.x), silu(f.y));
        }

        // stage 2: [64] -> [64], split into two output halves (reg pressure)
#pragma unroll
        for (int Hh = 0; Hh < 2; Hh++) {
            u64 acc[16];
#pragma unroll
            for (int m = 0; m < 16; m++) acc[m] = 0ull;
#pragma unroll 4
            for (int kk = 0; kk < 32; kk++) {
                float2 hk = unpk(h2[kk]);
                u64 a0 = pack2(hk.x, hk.x);
                u64 a1 = pack2(hk.y, hk.y);
                const ulonglong2* r0 = (const ulonglong2*)(sR2 + (2*kk)*HH   + Hh*32);
                const ulonglong2* r1 = (const ulonglong2*)(sR2 + (2*kk+1)*HH + Hh*32);
#pragma unroll
                for (int m = 0; m < 8; m++) {
                    ulonglong2 w0 = r0[m], w1 = r1[m];
                    ffma2(acc[2*m],   a0, w0.x);
                    ffma2(acc[2*m+1], a0, w0.y);
                    ffma2(acc[2*m],   a1, w1.x);
                    ffma2(acc[2*m+1], a1, w1.y);
                }
            }
#pragma unroll
            for (int m = 0; m < 16; m++) {
                float2 f = unpk(acc[m]);
                hw[(Hh*32 + 2*m)*32   + lane] = silu(f.x);
                hw[(Hh*32 + 2*m+1)*32 + lane] = silu(f.y);
            }
        }
        __syncwarp();

        // ======== phase B: lane = channel, 4 sub-batches of 8 edges ========
#pragma unroll 1
        for (int q = 0; q < 4; q++) {
            u64 acc[20];   // [p][pair]
#pragma unroll
            for (int i = 0; i < 20; i++) acc[i] = 0ull;
            const float* hq = hw + q*8;
#pragma unroll 4
            for (int k = 0; k < 64; k++) {
                ulonglong2 hA = *(const ulonglong2*)(hq + k*32);       // edges 0..3
                ulonglong2 hB = *(const ulonglong2*)(hq + k*32 + 4);   // edges 4..7
                const float* r3 = sR3 + k*5*CC + lane;
#pragma unroll
                for (int p = 0; p < 5; p++) {
                    float w = r3[p*CC];
                    u64 w2 = pack2(w, w);
                    ffma2(acc[p*4+0], hA.x, w2);
                    ffma2(acc[p*4+1], hA.y, w2);
                    ffma2(acc[p*4+2], hB.x, w2);
                    ffma2(acc[p*4+3], hB.y, w2);
                }
            }
            // TP message + atomic scatter for 8 edges
#pragma unroll
            for (int pr = 0; pr < 4; pr++) {
                float2 w0p = unpk(acc[0*4+pr]);
                float2 w1p = unpk(acc[1*4+pr]);
                float2 w2p = unpk(acc[2*4+pr]);
                float2 w3p = unpk(acc[3*4+pr]);
                float2 w4p = unpk(acc[4*4+pr]);
#pragma unroll
                for (int hh = 0; hh < 2; hh++) {
                    int eg = ebase + q*8 + pr*2 + hh;
                    float w0 = hh ? w0p.y : w0p.x;
                    float w1 = hh ? w1p.y : w1p.x;
                    float w2v= hh ? w2p.y : w2p.x;
                    float w3 = hh ? w3p.y : w3p.x;
                    float w4 = hh ? w4p.y : w4p.x;
                    int sI = __ldg(src + eg), dI = __ldg(dst + eg);
                    float y0 = __ldg(g_Y1 + eg*3 + 0);
                    float y1 = __ldg(g_Y1 + eg*3 + 1);
                    float y2 = __ldg(g_Y1 + eg*3 + 2);
                    float ss = g_su[sI*CC + lane];
                    const float* vp = g_vu + (sI*CC + lane)*3;
                    float v0 = vp[0], v1 = vp[1], v2 = vp[2];
                    float dot = v0*y0 + v1*y1 + v2*y2;
                    float c0 = v1*y2 - v2*y1;
                    float c1 = v2*y0 - v0*y2;
                    float c2 = v0*y1 - v1*y0;
                    float ms = w0*ss + w3*dot;
                    float m0 = w1*ss*y0 + w2v*v0 + w4*c0;
                    float m1 = w1*ss*y1 + w2v*v1 + w4*c1;
                    float m2 = w1*ss*y2 + w2v*v2 + w4*c2;
                    atomicAdd(&g_S[dI*CC + lane], ms);
                    float* op = g_V + (dI*CC + lane)*3;
                    atomicAdd(op + 0, m0);
                    atomicAdd(op + 1, m1);
                    atomicAdd(op + 2, m2);
                }
            }
        }
        __syncwarp();
    }
}

// ---------------- node update: out linears, skip, product block --------------
#define NWB 16
__global__ void k_nodeupd(const float* __restrict__ Wouts,
                          const float* __restrict__ Woutv,
                          const float* __restrict__ Wscs,
                          const float* __restrict__ Wscv,
                          const float* __restrict__ Wp,
                          const float* __restrict__ Wlins,
                          const float* __restrict__ Wlinv,
                          float* __restrict__ out, int l) {
    __shared__ float sWos[CC*CC], sWov[CC*CC], sWls[CC*CC], sWlv[CC*CC];
    __shared__ float st[NWB][256];
    int tid = threadIdx.x;
    for (int i = tid; i < CC*CC; i += blockDim.x) {
        sWos[i] = Wouts[i]; sWov[i] = Woutv[i];
        sWls[i] = Wlins[i]; sWlv[i] = Wlinv[i];
    }
    __syncthreads();
    int warp = tid >> 5, lane = tid & 31;
    int n = blockIdx.x * NWB + warp;
    if (n >= NN) return;

    float* xs = st[warp];
    float* xv = xs + 32;
    float* ys = xv + 96;
    float* yv = ys + 32;

    int z = g_z[n];
    int b = (n*CC + lane)*3;
    xs[lane]       = g_S[n*CC + lane] * INV_AVG;
    xv[lane*3 + 0] = g_V[b+0] * INV_AVG;
    xv[lane*3 + 1] = g_V[b+1] * INV_AVG;
    xv[lane*3 + 2] = g_V[b+2] * INV_AVG;
    ys[lane]       = g_s[n*CC + lane];
    yv[lane*3 + 0] = g_v[b+0];
    yv[lane*3 + 1] = g_v[b+1];
    yv[lane*3 + 2] = g_v[b+2];
    __syncwarp();

    const float* Ws = Wscs + z*CC*CC;
    const float* Wv = Wscv + z*CC*CC;
    float s2 = 0.f, v20 = 0.f, v21 = 0.f, v22 = 0.f;
    float scs = 0.f, sv0 = 0.f, sv1 = 0.f, sv2 = 0.f;
#pragma unroll
    for (int k = 0; k < CC; k++) {
        float wo = sWos[k*CC + lane], wvv = sWov[k*CC + lane];
        s2  += xs[k]     * wo;
        v20 += xv[k*3+0] * wvv;
        v21 += xv[k*3+1] * wvv;
        v22 += xv[k*3+2] * wvv;
        float as = __ldg(Ws + k*CC + lane), av = __ldg(Wv + k*CC + lane);
        scs += ys[k]     * as;
        sv0 += yv[k*3+0] * av;
        sv1 += yv[k*3+1] * av;
        sv2 += yv[k*3+2] * av;
    }

    float we0 = __ldg(Wp + (z*5+0)*CC + lane);
    float we1 = __ldg(Wp + (z*5+1)*CC + lane);
    float we2 = __ldg(Wp + (z*5+2)*CC + lane);
    float we3 = __ldg(Wp + (z*5+3)*CC + lane);
    float we4 = __ldg(Wp + (z*5+4)*CC + lane);

    float vdot = v20*v20 + v21*v21 + v22*v22;
    float ps  = we0*s2 + we1*s2*s2 + we2*vdot;
    float pv0 = we3*v20 + we4*s2*v20;
    float pv1 = we3*v21 + we4*s2*v21;
    float pv2 = we3*v22 + we4*s2*v22;
    __syncwarp();
    xs[lane] = ps;
    xv[lane*3+0] = pv0; xv[lane*3+1] = pv1; xv[lane*3+2] = pv2;
    __syncwarp();

    float sn = scs, vn0 = sv0, vn1 = sv1, vn2 = sv2;
#pragma unroll
    for (int k = 0; k < CC; k++) {
        float wl = sWls[k*CC + lane], wlv = sWlv[k*CC + lane];
        sn  += xs[k]     * wl;
        vn0 += xv[k*3+0] * wlv;
        vn1 += xv[k*3+1] * wlv;
        vn2 += xv[k*3+2] * wlv;
    }
    g_s[n*CC + lane] = sn;
    g_v[b+0] = vn0; g_v[b+1] = vn1; g_v[b+2] = vn2;
    out[n*(LL*CC) + l*CC + lane] = sn;
}

// ---------------- launch ------------------------------------------------------
extern "C" void kernel_launch(void* const* d_in, const int* in_sizes, int n_in,
                              void* d_out, int out_size) {
    const float* pos     = (const float*)d_in[0];
    const float* attrs   = (const float*)d_in[1];
    const float* shifts  = (const float*)d_in[2];
    const float* W_embed = (const float*)d_in[3];
    const float* W_up_s  = (const float*)d_in[4];
    const float* W_up_v  = (const float*)d_in[5];
    const float* R1      = (const float*)d_in[6];
    const float* R2      = (const float*)d_in[7];
    const float* R3      = (const float*)d_in[8];
    const float* W_out_s = (const float*)d_in[9];
    const float* W_out_v = (const float*)d_in[10];
    const float* Wsc_s   = (const float*)d_in[11];
    const float* Wsc_v   = (const float*)d_in[12];
    const float* Wp      = (const float*)d_in[13];
    const float* W_lin_s = (const float*)d_in[14];
    const float* W_lin_v = (const float*)d_in[15];
    const int*   ei      = (const int*)d_in[16];
    const int* src = ei;
    const int* dst = ei + EE;
    float* out = (float*)d_out;

    int smem = (NB*HH + HH*HH + HH*5*CC + EW*HWF) * (int)sizeof(float); // 108544 B
    cudaFuncSetAttribute(k_edge, cudaFuncAttributeMaxDynamicSharedMemorySize, smem);

    k_zidx <<<(NN + 255)/256, 256>>>(attrs);
    k_embed<<<(NN*CC + 255)/256, 256>>>(W_embed);
    k_geom <<<(EE + 255)/256, 256>>>(pos, shifts, src, dst);

    for (int l = 0; l < LL; l++) {
        k_nodeup<<<(NN + NWU - 1)/NWU, NWU*32>>>(W_up_s + l*CC*CC, W_up_v + l*CC*CC);
        k_zero  <<<(NN*CC*3 + 255)/256, 256>>>();
        k_edge  <<<296, ETPB, smem>>>(R1 + l*NB*HH, R2 + l*HH*HH, R3 + l*HH*5*CC, src, dst);
        k_nodeupd<<<(NN + NWB - 1)/NWB, NWB*32>>>(
            W_out_s + l*CC*CC, W_out_v + l*CC*CC,
            Wsc_s + l*ZZ*CC*CC, Wsc_v + l*ZZ*CC*CC, Wp + l*ZZ*5*CC,
            W_lin_s + l*CC*CC, W_lin_v + l*CC*CC, out, l);
    }
}

// round 5
// speedup vs baseline: 1.0931x; 1.0931x over previous
#include <cuda_runtime.h>
#include <math.h>

#define NN 50000
#define EE 800000
#define CC 32
#define ZZ 10
#define LL 2
#define NB 8
#define HH 64
#define INV_AVG (1.0f/16.0f)
#define RCUT_INV (1.0f/5.0f)

typedef unsigned long long u64;

// ---------------- scratch (static device globals; no allocation) -------------
__device__ float4 g_sv [NN*CC];   // {s, v0, v1, v2}
__device__ float4 g_up [NN*CC];   // {su, vu0, vu1, vu2}
__device__ float4 g_acc[NN*CC];   // {S, V0, V1, V2}
__device__ float4 g_Y1 [EE];      // {y0, y1, y2, pad}
__device__ float  g_ef [EE*NB];
__device__ int    g_z  [NN];

// ---------------- packed fp32x2 helpers (SASS FFMA2 via PTX) -----------------
__device__ __forceinline__ u64 pack2(float lo, float hi) {
    u64 r; asm("mov.b64 %0, {%1,%2};" : "=l"(r) : "f"(lo), "f"(hi)); return r;
}
__device__ __forceinline__ float2 unpk(u64 v) {
    float2 f; asm("mov.b64 {%0,%1}, %2;" : "=f"(f.x), "=f"(f.y) : "l"(v)); return f;
}
__device__ __forceinline__ void ffma2(u64 &d, u64 a, u64 b) {
    asm("fma.rn.f32x2 %0, %1, %2, %0;" : "+l"(d) : "l"(a), "l"(b));
}
__device__ __forceinline__ float silu(float x) {
    return __fdividef(x, 1.0f + __expf(-x));
}
__device__ __forceinline__ void red_v4(float4* p, float a, float b, float c, float d) {
    asm volatile("red.global.add.v4.f32 [%0], {%1,%2,%3,%4};"
                 :: "l"(p), "f"(a), "f"(b), "f"(c), "f"(d) : "memory");
}

// ---------------- species index from one-hot ---------------------------------
__global__ void k_zidx(const float* __restrict__ attrs) {
    int n = blockIdx.x * blockDim.x + threadIdx.x;
    if (n >= NN) return;
    int z = 0;
#pragma unroll
    for (int j = 0; j < ZZ; j++)
        if (attrs[n*ZZ + j] > 0.5f) z = j;
    g_z[n] = z;
}

// ---------------- s = onehot @ W_embed, v = 0 --------------------------------
__global__ void k_embed(const float* __restrict__ W_embed) {
    int idx = blockIdx.x * blockDim.x + threadIdx.x;
    if (idx >= NN*CC) return;
    int n = idx >> 5, c = idx & 31;
    g_sv[idx] = make_float4(W_embed[g_z[n]*CC + c], 0.f, 0.f, 0.f);
}

// ---------------- edge geometry: Y1 + radial features ------------------------
__global__ void k_geom(const float* __restrict__ pos,
                       const float* __restrict__ shifts,
                       const int* __restrict__ src,
                       const int* __restrict__ dst) {
    int e = blockIdx.x * blockDim.x + threadIdx.x;
    if (e >= EE) return;
    int si = src[e], di = dst[e];
    float vx = pos[di*3+0] - pos[si*3+0] + shifts[e*3+0];
    float vy = pos[di*3+1] - pos[si*3+1] + shifts[e*3+1];
    float vz = pos[di*3+2] - pos[si*3+2] + shifts[e*3+2];
    float r  = sqrtf(vx*vx + vy*vy + vz*vz);
    float rs = fmaxf(r, 1e-9f);
    float inv = 1.0f / rs;
    g_Y1[e] = make_float4(vx*inv, vy*inv, vz*inv, 0.f);
    float x = r * RCUT_INV;
    float fc = 0.f;
    if (x < 1.0f) {
        float x2 = x*x, x3 = x2*x;
        float x6 = x3*x3, x7 = x6*x, x8 = x7*x;
        fc = 1.0f - 28.0f*x6 + 48.0f*x7 - 21.0f*x8;   // P=6 polynomial cutoff
    }
    float coef = 0.6324555320336759f * fc * inv;       // sqrt(2/RCUT)*fc/rs
    float arg0 = rs * (float)M_PI * RCUT_INV;
#pragma unroll
    for (int nb = 0; nb < NB; nb++)
        g_ef[e*NB + nb] = coef * sinf((float)(nb+1) * arg0);
}

// ---------------- node "up" linears: su = s@Wus, vu = v@Wuv ------------------
#define NWU 16
__global__ void k_nodeup(const float* __restrict__ Wus,
                         const float* __restrict__ Wuv) {
    __shared__ float sWs[CC*CC], sWv[CC*CC];
    __shared__ float st[NWU][128];
    int tid = threadIdx.x;
    for (int i = tid; i < CC*CC; i += blockDim.x) { sWs[i] = Wus[i]; sWv[i] = Wuv[i]; }
    __syncthreads();
    int warp = tid >> 5, lane = tid & 31;
    int n = blockIdx.x * NWU + warp;
    if (n >= NN) return;
    float* xs = st[warp];
    float* xv = st[warp] + 32;
    float4 f = g_sv[n*CC + lane];
    xs[lane]       = f.x;
    xv[lane*3 + 0] = f.y;
    xv[lane*3 + 1] = f.z;
    xv[lane*3 + 2] = f.w;
    __syncwarp();
    float a = 0.f, u0 = 0.f, u1 = 0.f, u2 = 0.f;
#pragma unroll
    for (int k = 0; k < CC; k++) {
        float ws = sWs[k*CC + lane], wv = sWv[k*CC + lane];
        a  += xs[k]     * ws;
        u0 += xv[k*3+0] * wv;
        u1 += xv[k*3+1] * wv;
        u2 += xv[k*3+2] * wv;
    }
    g_up[n*CC + lane] = make_float4(a, u0, u1, u2);
}

// ---------------- zero accumulators ------------------------------------------
__global__ void k_zero() {
    int i = blockIdx.x * blockDim.x + threadIdx.x;
    if (i < NN*CC) g_acc[i] = make_float4(0.f, 0.f, 0.f, 0.f);
}

// ---------------- fused edge kernel ------------------------------------------
// Phase A (lane = edge): radial MLP stages 1-2 with broadcast LDS.128 weights
//   and FFMA2 packed math; silu'd hidden written transposed to per-warp smem.
// Phase B (lane = channel): stage-3 [64 -> 5x32] register-blocked over 8-edge
//   sub-batches (f32x2 over edge pairs), then TP message + vec4 atomic scatter.
#define EW 6
#define ETPB (EW*32)
#define HWF 2048   // 64*32 floats per warp

__global__ void __launch_bounds__(ETPB, 2)
k_edge(const float* __restrict__ R1,
       const float* __restrict__ R2,
       const float* __restrict__ R3,
       const int*  __restrict__ src,
       const int*  __restrict__ dst) {
    extern __shared__ float smf[];
    float* sR1  = smf;                      // 512
    float* sR2  = sR1 + NB*HH;              // 4096
    float* sR3  = sR2 + HH*HH;              // 10240
    float* hall = sR3 + HH*5*CC;            // EW*2048
    int tid = threadIdx.x;
    for (int i = tid; i < NB*HH;   i += ETPB) sR1[i] = R1[i];
    for (int i = tid; i < HH*HH;   i += ETPB) sR2[i] = R2[i];
    for (int i = tid; i < HH*5*CC; i += ETPB) sR3[i] = R3[i];
    __syncthreads();

    int warp = tid >> 5, lane = tid & 31;
    float* hw = hall + warp*HWF;
    const int nbatch = EE/32;   // 25000, exact

    for (int b = blockIdx.x*EW + warp; b < nbatch; b += gridDim.x*EW) {
        int ebase = b*32;
        int e = ebase + lane;

        // ======== phase A: lane = edge ========
        float4 efa = *(const float4*)&g_ef[e*NB];
        float4 efb = *(const float4*)&g_ef[e*NB + 4];
        float ef[8] = {efa.x, efa.y, efa.z, efa.w, efb.x, efb.y, efb.z, efb.w};

        // stage 1: [8] -> [64]
        u64 h2[32];
#pragma unroll
        for (int m = 0; m < 32; m++) h2[m] = 0ull;
#pragma unroll
        for (int k = 0; k < 8; k++) {
            u64 a = pack2(ef[k], ef[k]);
            const ulonglong2* row = (const ulonglong2*)(sR1 + k*HH);
#pragma unroll
            for (int m = 0; m < 16; m++) {
                ulonglong2 w = row[m];
                ffma2(h2[2*m],   a, w.x);
                ffma2(h2[2*m+1], a, w.y);
            }
        }
#pragma unroll
        for (int m = 0; m < 32; m++) {
            float2 f = unpk(h2[m]);
            h2[m] = pack2(silu(f.x), silu(f.y));
        }

        // stage 2: [64] -> [64], split into two output halves (reg pressure)
#pragma unroll
        for (int Hh = 0; Hh < 2; Hh++) {
            u64 acc[16];
#pragma unroll
            for (int m = 0; m < 16; m++) acc[m] = 0ull;
#pragma unroll 4
            for (int kk = 0; kk < 32; kk++) {
                float2 hk = unpk(h2[kk]);
                u64 a0 = pack2(hk.x, hk.x);
                u64 a1 = pack2(hk.y, hk.y);
                const ulonglong2* r0 = (const ulonglong2*)(sR2 + (2*kk)*HH   + Hh*32);
                const ulonglong2* r1 = (const ulonglong2*)(sR2 + (2*kk+1)*HH + Hh*32);
#pragma unroll
                for (int m = 0; m < 8; m++) {
                    ulonglong2 w0 = r0[m], w1 = r1[m];
                    ffma2(acc[2*m],   a0, w0.x);
                    ffma2(acc[2*m+1], a0, w0.y);
                    ffma2(acc[2*m],   a1, w1.x);
                    ffma2(acc[2*m+1], a1, w1.y);
                }
            }
#pragma unroll
            for (int m = 0; m < 16; m++) {
                float2 f = unpk(acc[m]);
                hw[(Hh*32 + 2*m)*32   + lane] = silu(f.x);
                hw[(Hh*32 + 2*m+1)*32 + lane] = silu(f.y);
            }
        }
        __syncwarp();

        // ======== phase B: lane = channel, 4 sub-batches of 8 edges ========
#pragma unroll 1
        for (int q = 0; q < 4; q++) {
            u64 acc[20];   // [p][pair]
#pragma unroll
            for (int i = 0; i < 20; i++) acc[i] = 0ull;
            const float* hq = hw + q*8;
#pragma unroll 4
            for (int k = 0; k < 64; k++) {
                ulonglong2 hA = *(const ulonglong2*)(hq + k*32);       // edges 0..3
                ulonglong2 hB = *(const ulonglong2*)(hq + k*32 + 4);   // edges 4..7
                const float* r3 = sR3 + k*5*CC + lane;
#pragma unroll
                for (int p = 0; p < 5; p++) {
                    float w = r3[p*CC];
                    u64 w2 = pack2(w, w);
                    ffma2(acc[p*4+0], hA.x, w2);
                    ffma2(acc[p*4+1], hA.y, w2);
                    ffma2(acc[p*4+2], hB.x, w2);
                    ffma2(acc[p*4+3], hB.y, w2);
                }
            }
            // TP message + vec4 atomic scatter for 8 edges
#pragma unroll
            for (int pr = 0; pr < 4; pr++) {
                float2 w0p = unpk(acc[0*4+pr]);
                float2 w1p = unpk(acc[1*4+pr]);
                float2 w2p = unpk(acc[2*4+pr]);
                float2 w3p = unpk(acc[3*4+pr]);
                float2 w4p = unpk(acc[4*4+pr]);
#pragma unroll
                for (int hh = 0; hh < 2; hh++) {
                    int eg = ebase + q*8 + pr*2 + hh;
                    float w0 = hh ? w0p.y : w0p.x;
                    float w1 = hh ? w1p.y : w1p.x;
                    float w2v= hh ? w2p.y : w2p.x;
                    float w3 = hh ? w3p.y : w3p.x;
                    float w4 = hh ? w4p.y : w4p.x;
                    int sI = __ldg(src + eg), dI = __ldg(dst + eg);
                    float4 y4 = __ldg(g_Y1 + eg);
                    float y0 = y4.x, y1 = y4.y, y2 = y4.z;
                    float4 uv = __ldg(g_up + sI*CC + lane);
                    float ss = uv.x, v0 = uv.y, v1 = uv.z, v2 = uv.w;
                    float dot = v0*y0 + v1*y1 + v2*y2;
                    float c0 = v1*y2 - v2*y1;
                    float c1 = v2*y0 - v0*y2;
                    float c2 = v0*y1 - v1*y0;
                    float ms = w0*ss + w3*dot;
                    float m0 = w1*ss*y0 + w2v*v0 + w4*c0;
                    float m1 = w1*ss*y1 + w2v*v1 + w4*c1;
                    float m2 = w1*ss*y2 + w2v*v2 + w4*c2;
                    red_v4(g_acc + dI*CC + lane, ms, m0, m1, m2);
                }
            }
        }
        __syncwarp();
    }
}

// ---------------- node update: out linears, skip, product block --------------
#define NWB 16
__global__ void k_nodeupd(const float* __restrict__ Wouts,
                          const float* __restrict__ Woutv,
                          const float* __restrict__ Wscs,
                          const float* __restrict__ Wscv,
                          const float* __restrict__ Wp,
                          const float* __restrict__ Wlins,
                          const float* __restrict__ Wlinv,
                          float* __restrict__ out, int l) {
    __shared__ float sWos[CC*CC], sWov[CC*CC], sWls[CC*CC], sWlv[CC*CC];
    __shared__ float st[NWB][256];
    int tid = threadIdx.x;
    for (int i = tid; i < CC*CC; i += blockDim.x) {
        sWos[i] = Wouts[i]; sWov[i] = Woutv[i];
        sWls[i] = Wlins[i]; sWlv[i] = Wlinv[i];
    }
    __syncthreads();
    int warp = tid >> 5, lane = tid & 31;
    int n = blockIdx.x * NWB + warp;
    if (n >= NN) return;

    float* xs = st[warp];
    float* xv = xs + 32;
    float* ys = xv + 96;
    float* yv = ys + 32;

    int z = g_z[n];
    float4 a4 = g_acc[n*CC + lane];
    float4 o4 = g_sv [n*CC + lane];
    xs[lane]       = a4.x * INV_AVG;
    xv[lane*3 + 0] = a4.y * INV_AVG;
    xv[lane*3 + 1] = a4.z * INV_AVG;
    xv[lane*3 + 2] = a4.w * INV_AVG;
    ys[lane]       = o4.x;
    yv[lane*3 + 0] = o4.y;
    yv[lane*3 + 1] = o4.z;
    yv[lane*3 + 2] = o4.w;
    __syncwarp();

    const float* Ws = Wscs + z*CC*CC;
    const float* Wv = Wscv + z*CC*CC;
    float s2 = 0.f, v20 = 0.f, v21 = 0.f, v22 = 0.f;
    float scs = 0.f, sv0 = 0.f, sv1 = 0.f, sv2 = 0.f;
#pragma unroll
    for (int k = 0; k < CC; k++) {
        float wo = sWos[k*CC + lane], wvv = sWov[k*CC + lane];
        s2  += xs[k]     * wo;
        v20 += xv[k*3+0] * wvv;
        v21 += xv[k*3+1] * wvv;
        v22 += xv[k*3+2] * wvv;
        float as = __ldg(Ws + k*CC + lane), av = __ldg(Wv + k*CC + lane);
        scs += ys[k]     * as;
        sv0 += yv[k*3+0] * av;
        sv1 += yv[k*3+1] * av;
        sv2 += yv[k*3+2] * av;
    }

    float we0 = __ldg(Wp + (z*5+0)*CC + lane);
    float we1 = __ldg(Wp + (z*5+1)*CC + lane);
    float we2 = __ldg(Wp + (z*5+2)*CC + lane);
    float we3 = __ldg(Wp + (z*5+3)*CC + lane);
    float we4 = __ldg(Wp + (z*5+4)*CC + lane);

    float vdot = v20*v20 + v21*v21 + v22*v22;
    float ps  = we0*s2 + we1*s2*s2 + we2*vdot;
    float pv0 = we3*v20 + we4*s2*v20;
    float pv1 = we3*v21 + we4*s2*v21;
    float pv2 = we3*v22 + we4*s2*v22;
    __syncwarp();
    xs[lane] = ps;
    xv[lane*3+0] = pv0; xv[lane*3+1] = pv1; xv[lane*3+2] = pv2;
    __syncwarp();

    float sn = scs, vn0 = sv0, vn1 = sv1, vn2 = sv2;
#pragma unroll
    for (int k = 0; k < CC; k++) {
        float wl = sWls[k*CC + lane], wlv = sWlv[k*CC + lane];
        sn  += xs[k]     * wl;
        vn0 += xv[k*3+0] * wlv;
        vn1 += xv[k*3+1] * wlv;
        vn2 += xv[k*3+2] * wlv;
    }
    g_sv[n*CC + lane] = make_float4(sn, vn0, vn1, vn2);
    out[n*(LL*CC) + l*CC + lane] = sn;
}

// ---------------- launch ------------------------------------------------------
extern "C" void kernel_launch(void* const* d_in, const int* in_sizes, int n_in,
                              void* d_out, int out_size) {
    const float* pos     = (const float*)d_in[0];
    const float* attrs   = (const float*)d_in[1];
    const float* shifts  = (const float*)d_in[2];
    const float* W_embed = (const float*)d_in[3];
    const float* W_up_s  = (const float*)d_in[4];
    const float* W_up_v  = (const float*)d_in[5];
    const float* R1      = (const float*)d_in[6];
    const float* R2      = (const float*)d_in[7];
    const float* R3      = (const float*)d_in[8];
    const float* W_out_s = (const float*)d_in[9];
    const float* W_out_v = (const float*)d_in[10];
    const float* Wsc_s   = (const float*)d_in[11];
    const float* Wsc_v   = (const float*)d_in[12];
    const float* Wp      = (const float*)d_in[13];
    const float* W_lin_s = (const float*)d_in[14];
    const float* W_lin_v = (const float*)d_in[15];
    const int*   ei      = (const int*)d_in[16];
    const int* src = ei;
    const int* dst = ei + EE;
    float* out = (float*)d_out;

    int smem = (NB*HH + HH*HH + HH*5*CC + EW*HWF) * (int)sizeof(float); // 108544 B
    cudaFuncSetAttribute(k_edge, cudaFuncAttributeMaxDynamicSharedMemorySize, smem);

    k_zidx <<<(NN + 255)/256, 256>>>(attrs);
    k_embed<<<(NN*CC + 255)/256, 256>>>(W_embed);
    k_geom <<<(EE + 255)/256, 256>>>(pos, shifts, src, dst);

    for (int l = 0; l < LL; l++) {
        k_nodeup<<<(NN + NWU - 1)/NWU, NWU*32>>>(W_up_s + l*CC*CC, W_up_v + l*CC*CC);
        k_zero  <<<(NN*CC + 255)/256, 256>>>();
        k_edge  <<<296, ETPB, smem>>>(R1 + l*NB*HH, R2 + l*HH*HH, R3 + l*HH*5*CC, src, dst);
        k_nodeupd<<<(NN + NWB - 1)/NWB, NWB*32>>>(
            W_out_s + l*CC*CC, W_out_v + l*CC*CC,
            Wsc_s + l*ZZ*CC*CC, Wsc_v + l*ZZ*CC*CC, Wp + l*ZZ*5*CC,
            W_lin_s + l*CC*CC, W_lin_v + l*CC*CC, out, l);
    }
}

// round 7
// speedup vs baseline: 1.1180x; 1.0228x over previous
#include <cuda_runtime.h>
#include <math.h>

#define NN 50000
#define EE 800000
#define CC 32
#define ZZ 10
#define LL 2
#define NB 8
#define HH 64
#define INV_AVG (1.0f/16.0f)
#define RCUT_INV (1.0f/5.0f)

typedef unsigned long long u64;

// ---------------- scratch (static device globals; no allocation) -------------
__device__ float4 g_sv [NN*CC];   // {s, v0, v1, v2}
__device__ float4 g_up [NN*CC];   // {su, vu0, vu1, vu2}
__device__ float4 g_acc[NN*CC];   // {S, V0, V1, V2}
__device__ float4 g_Y1 [EE];      // {y0, y1, y2, pad}
__device__ float  g_ef [EE*NB];
__device__ int    g_z  [NN];

// ---------------- packed fp32x2 helpers (SASS FFMA2 via PTX) -----------------
__device__ __forceinline__ u64 pack2(float lo, float hi) {
    u64 r; asm("mov.b64 %0, {%1,%2};" : "=l"(r) : "f"(lo), "f"(hi)); return r;
}
__device__ __forceinline__ float2 unpk(u64 v) {
    float2 f; asm("mov.b64 {%0,%1}, %2;" : "=f"(f.x), "=f"(f.y) : "l"(v)); return f;
}
__device__ __forceinline__ void ffma2(u64 &d, u64 a, u64 b) {
    asm("fma.rn.f32x2 %0, %1, %2, %0;" : "+l"(d) : "l"(a), "l"(b));
}
__device__ __forceinline__ float silu(float x) {
    return __fdividef(x, 1.0f + __expf(-x));
}
__device__ __forceinline__ void red_v4(float4* p, float a, float b, float c, float d) {
    asm volatile("red.global.add.v4.f32 [%0], {%1,%2,%3,%4};"
                 :: "l"(p), "f"(a), "f"(b), "f"(c), "f"(d) : "memory");
}

// ---------------- species index from one-hot ---------------------------------
__global__ void k_zidx(const float* __restrict__ attrs) {
    int n = blockIdx.x * blockDim.x + threadIdx.x;
    if (n >= NN) return;
    int z = 0;
#pragma unroll
    for (int j = 0; j < ZZ; j++)
        if (attrs[n*ZZ + j] > 0.5f) z = j;
    g_z[n] = z;
}

// ---------------- s = onehot @ W_embed, v = 0 --------------------------------
__global__ void k_embed(const float* __restrict__ W_embed) {
    int idx = blockIdx.x * blockDim.x + threadIdx.x;
    if (idx >= NN*CC) return;
    int n = idx >> 5, c = idx & 31;
    g_sv[idx] = make_float4(W_embed[g_z[n]*CC + c], 0.f, 0.f, 0.f);
}

// ---------------- edge geometry: Y1 + radial features ------------------------
// NOTE: precise sinf per basis fn — fast-math trig here fails the 1e-3 gate.
__global__ void k_geom(const float* __restrict__ pos,
                       const float* __restrict__ shifts,
                       const int* __restrict__ src,
                       const int* __restrict__ dst) {
    int e = blockIdx.x * blockDim.x + threadIdx.x;
    if (e >= EE) return;
    int si = src[e], di = dst[e];
    float vx = pos[di*3+0] - pos[si*3+0] + shifts[e*3+0];
    float vy = pos[di*3+1] - pos[si*3+1] + shifts[e*3+1];
    float vz = pos[di*3+2] - pos[si*3+2] + shifts[e*3+2];
    float r  = sqrtf(vx*vx + vy*vy + vz*vz);
    float rs = fmaxf(r, 1e-9f);
    float inv = 1.0f / rs;
    g_Y1[e] = make_float4(vx*inv, vy*inv, vz*inv, 0.f);
    float x = r * RCUT_INV;
    float fc = 0.f;
    if (x < 1.0f) {
        float x2 = x*x, x3 = x2*x;
        float x6 = x3*x3, x7 = x6*x, x8 = x7*x;
        fc = 1.0f - 28.0f*x6 + 48.0f*x7 - 21.0f*x8;   // P=6 polynomial cutoff
    }
    float coef = 0.6324555320336759f * fc * inv;       // sqrt(2/RCUT)*fc/rs
    float arg0 = rs * (float)M_PI * RCUT_INV;
#pragma unroll
    for (int nb = 0; nb < NB; nb++)
        g_ef[e*NB + nb] = coef * sinf((float)(nb+1) * arg0);
}

// ---------------- node "up" linears: su = s@Wus, vu = v@Wuv (+zero acc) ------
#define NWU 16
__global__ void k_nodeup(const float* __restrict__ Wus,
                         const float* __restrict__ Wuv) {
    __shared__ float sWs[CC*CC], sWv[CC*CC];
    __shared__ float st[NWU][128];
    int tid = threadIdx.x;
    for (int i = tid; i < CC*CC; i += blockDim.x) { sWs[i] = Wus[i]; sWv[i] = Wuv[i]; }
    __syncthreads();
    int warp = tid >> 5, lane = tid & 31;
    int n = blockIdx.x * NWU + warp;
    if (n >= NN) return;
    float* xs = st[warp];
    float* xv = st[warp] + 32;
    float4 f = g_sv[n*CC + lane];
    g_acc[n*CC + lane] = make_float4(0.f, 0.f, 0.f, 0.f);   // zero accumulators here
    xs[lane]       = f.x;
    xv[lane*3 + 0] = f.y;
    xv[lane*3 + 1] = f.z;
    xv[lane*3 + 2] = f.w;
    __syncwarp();
    float a = 0.f, u0 = 0.f, u1 = 0.f, u2 = 0.f;
#pragma unroll
    for (int k = 0; k < CC; k++) {
        float ws = sWs[k*CC + lane], wv = sWv[k*CC + lane];
        a  += xs[k]     * ws;
        u0 += xv[k*3+0] * wv;
        u1 += xv[k*3+1] * wv;
        u2 += xv[k*3+2] * wv;
    }
    g_up[n*CC + lane] = make_float4(a, u0, u1, u2);
}

// ---------------- fused edge kernel ------------------------------------------
// Phase A (lane = edge): radial MLP stages 1-2 with broadcast LDS.128 weights
//   and FFMA2 packed math; silu'd hidden written transposed to per-warp smem.
// Phase B (lane = channel): stage-3 [64 -> 5x32] register-blocked over 8-edge
//   sub-batches. R3 transposed in smem to [p][c][kpad=68] so weight loads are
//   LDS.128 over 4 k's; epilogue gathers hoisted above the k-loop.
#define EW 6
#define ETPB (EW*32)
#define HWF 2048          // 64*32 floats per warp
#define KP 68             // padded k stride (272B, conflict-free, 16B-aligned)

__global__ void __launch_bounds__(ETPB, 2)
k_edge(const float* __restrict__ R1,
       const float* __restrict__ R2,
       const float* __restrict__ R3,
       const int*  __restrict__ src,
       const int*  __restrict__ dst) {
    extern __shared__ float smf[];
    float* sR1  = smf;                      // 512
    float* sR2  = sR1 + NB*HH;              // 4096
    float* sR3T = sR2 + HH*HH;              // 5*32*68 = 10880
    float* hall = sR3T + 5*CC*KP;           // EW*2048
    int tid = threadIdx.x;
    for (int i = tid; i < NB*HH;   i += ETPB) sR1[i] = R1[i];
    for (int i = tid; i < HH*HH;   i += ETPB) sR2[i] = R2[i];
    for (int i = tid; i < 5*CC*HH; i += ETPB) {
        int k = i & 63, rest = i >> 6;
        int c = rest & 31, p = rest >> 5;
        sR3T[p*(CC*KP) + c*KP + k] = R3[k*5*CC + p*CC + c];
    }
    __syncthreads();

    int warp = tid >> 5, lane = tid & 31;
    float* hw = hall + warp*HWF;
    const int nbatch = EE/32;   // 25000, exact

    for (int b = blockIdx.x*EW + warp; b < nbatch; b += gridDim.x*EW) {
        int ebase = b*32;
        int e = ebase + lane;

        // ======== phase A: lane = edge ========
        float4 efa = *(const float4*)&g_ef[e*NB];
        float4 efb = *(const float4*)&g_ef[e*NB + 4];
        float ef[8] = {efa.x, efa.y, efa.z, efa.w, efb.x, efb.y, efb.z, efb.w};

        // stage 1: [8] -> [64]
        u64 h2[32];
#pragma unroll
        for (int m = 0; m < 32; m++) h2[m] = 0ull;
#pragma unroll
        for (int k = 0; k < 8; k++) {
            u64 a = pack2(ef[k], ef[k]);
            const ulonglong2* row = (const ulonglong2*)(sR1 + k*HH);
#pragma unroll
            for (int m = 0; m < 16; m++) {
                ulonglong2 w = row[m];
                ffma2(h2[2*m],   a, w.x);
                ffma2(h2[2*m+1], a, w.y);
            }
        }
#pragma unroll
        for (int m = 0; m < 32; m++) {
            float2 f = unpk(h2[m]);
            h2[m] = pack2(silu(f.x), silu(f.y));
        }

        // stage 2: [64] -> [64], split into two output halves (reg pressure)
#pragma unroll
        for (int Hh = 0; Hh < 2; Hh++) {
            u64 acc[16];
#pragma unroll
            for (int m = 0; m < 16; m++) acc[m] = 0ull;
#pragma unroll 4
            for (int kk = 0; kk < 32; kk++) {
                float2 hk = unpk(h2[kk]);
                u64 a0 = pack2(hk.x, hk.x);
                u64 a1 = pack2(hk.y, hk.y);
                const ulonglong2* r0 = (const ulonglong2*)(sR2 + (2*kk)*HH   + Hh*32);
                const ulonglong2* r1 = (const ulonglong2*)(sR2 + (2*kk+1)*HH + Hh*32);
#pragma unroll
                for (int m = 0; m < 8; m++) {
                    ulonglong2 w0 = r0[m], w1 = r1[m];
                    ffma2(acc[2*m],   a0, w0.x);
                    ffma2(acc[2*m+1], a0, w0.y);
                    ffma2(acc[2*m],   a1, w1.x);
                    ffma2(acc[2*m+1], a1, w1.y);
                }
            }
#pragma unroll
            for (int m = 0; m < 16; m++) {
                float2 f = unpk(acc[m]);
                hw[(Hh*32 + 2*m)*32   + lane] = silu(f.x);
                hw[(Hh*32 + 2*m+1)*32 + lane] = silu(f.y);
            }
        }
        __syncwarp();

        // ======== phase B: lane = channel, 4 sub-batches of 8 edges ========
#pragma unroll 1
        for (int q = 0; q < 4; q++) {
            // hoisted gathers for this sub-batch's 8 edges (overlap with k-loop)
            int eg0 = ebase + q*8;
            float4 uv8[8];
            float  yx[8], yy[8], yz[8];
            int    d8[8];
#pragma unroll
            for (int j = 0; j < 8; j++) {
                int eg = eg0 + j;
                int sI = __ldg(src + eg);
                d8[j]  = __ldg(dst + eg);
                float4 y4 = __ldg(g_Y1 + eg);
                yx[j] = y4.x; yy[j] = y4.y; yz[j] = y4.z;
                uv8[j] = __ldg(g_up + sI*CC + lane);
            }

            u64 acc[20];   // [p][pair]
#pragma unroll
            for (int i = 0; i < 20; i++) acc[i] = 0ull;
            const float* hq = hw + q*8;
            const float* r3base = sR3T + lane*KP;
#pragma unroll 2
            for (int k4 = 0; k4 < 16; k4++) {
                ulonglong2 hA[4], hB[4];
#pragma unroll
                for (int kk = 0; kk < 4; kk++) {
                    hA[kk] = *(const ulonglong2*)(hq + (4*k4+kk)*32);
                    hB[kk] = *(const ulonglong2*)(hq + (4*k4+kk)*32 + 4);
                }
#pragma unroll
                for (int p = 0; p < 5; p++) {
                    float4 w4 = *(const float4*)(r3base + p*(CC*KP) + 4*k4);
                    float wv[4] = {w4.x, w4.y, w4.z, w4.w};
#pragma unroll
                    for (int kk = 0; kk < 4; kk++) {
                        u64 w2 = pack2(wv[kk], wv[kk]);
                        ffma2(acc[p*4+0], hA[kk].x, w2);
                        ffma2(acc[p*4+1], hA[kk].y, w2);
                        ffma2(acc[p*4+2], hB[kk].x, w2);
                        ffma2(acc[p*4+3], hB[kk].y, w2);
                    }
                }
            }

            // TP message + vec4 atomic scatter for 8 edges
#pragma unroll
            for (int pr = 0; pr < 4; pr++) {
                float2 w0p = unpk(acc[0*4+pr]);
                float2 w1p = unpk(acc[1*4+pr]);
                float2 w2p = unpk(acc[2*4+pr]);
                float2 w3p = unpk(acc[3*4+pr]);
                float2 w4p = unpk(acc[4*4+pr]);
#pragma unroll
                for (int hh = 0; hh < 2; hh++) {
                    int j = pr*2 + hh;
                    float w0 = hh ? w0p.y : w0p.x;
                    float w1 = hh ? w1p.y : w1p.x;
                    float w2v= hh ? w2p.y : w2p.x;
                    float w3 = hh ? w3p.y : w3p.x;
                    float w4 = hh ? w4p.y : w4p.x;
                    float y0 = yx[j], y1 = yy[j], y2 = yz[j];
                    float ss = uv8[j].x, v0 = uv8[j].y, v1 = uv8[j].z, v2 = uv8[j].w;
                    float dot = v0*y0 + v1*y1 + v2*y2;
                    float c0 = v1*y2 - v2*y1;
                    float c1 = v2*y0 - v0*y2;
                    float c2 = v0*y1 - v1*y0;
                    float ms = w0*ss + w3*dot;
                    float m0 = w1*ss*y0 + w2v*v0 + w4*c0;
                    float m1 = w1*ss*y1 + w2v*v1 + w4*c1;
                    float m2 = w1*ss*y2 + w2v*v2 + w4*c2;
                    red_v4(g_acc + d8[j]*CC + lane, ms, m0, m1, m2);
                }
            }
        }
        __syncwarp();
    }
}

// ---------------- node update: out linears, skip, product block --------------
#define NWB 16
__global__ void k_nodeupd(const float* __restrict__ Wouts,
                          const float* __restrict__ Woutv,
                          const float* __restrict__ Wscs,
                          const float* __restrict__ Wscv,
                          const float* __restrict__ Wp,
                          const float* __restrict__ Wlins,
                          const float* __restrict__ Wlinv,
                          float* __restrict__ out, int l) {
    __shared__ float sWos[CC*CC], sWov[CC*CC], sWls[CC*CC], sWlv[CC*CC];
    __shared__ float st[NWB][256];
    int tid = threadIdx.x;
    for (int i = tid; i < CC*CC; i += blockDim.x) {
        sWos[i] = Wouts[i]; sWov[i] = Woutv[i];
        sWls[i] = Wlins[i]; sWlv[i] = Wlinv[i];
    }
    __syncthreads();
    int warp = tid >> 5, lane = tid & 31;
    int n = blockIdx.x * NWB + warp;
    if (n >= NN) return;

    float* xs = st[warp];
    float* xv = xs + 32;
    float* ys = xv + 96;
    float* yv = ys + 32;

    int z = g_z[n];
    float4 a4 = g_acc[n*CC + lane];
    float4 o4 = g_sv [n*CC + lane];
    xs[lane]       = a4.x * INV_AVG;
    xv[lane*3 + 0] = a4.y * INV_AVG;
    xv[lane*3 + 1] = a4.z * INV_AVG;
    xv[lane*3 + 2] = a4.w * INV_AVG;
    ys[lane]       = o4.x;
    yv[lane*3 + 0] = o4.y;
    yv[lane*3 + 1] = o4.z;
    yv[lane*3 + 2] = o4.w;
    __syncwarp();

    const float* Ws = Wscs + z*CC*CC;
    const float* Wv = Wscv + z*CC*CC;
    float s2 = 0.f, v20 = 0.f, v21 = 0.f, v22 = 0.f;
    float scs = 0.f, sv0 = 0.f, sv1 = 0.f, sv2 = 0.f;
#pragma unroll
    for (int k = 0; k < CC; k++) {
        float wo = sWos[k*CC + lane], wvv = sWov[k*CC + lane];
        s2  += xs[k]     * wo;
        v20 += xv[k*3+0] * wvv;
        v21 += xv[k*3+1] * wvv;
        v22 += xv[k*3+2] * wvv;
        float as = __ldg(Ws + k*CC + lane), av = __ldg(Wv + k*CC + lane);
        scs += ys[k]     * as;
        sv0 += yv[k*3+0] * av;
        sv1 += yv[k*3+1] * av;
        sv2 += yv[k*3+2] * av;
    }

    float we0 = __ldg(Wp + (z*5+0)*CC + lane);
    float we1 = __ldg(Wp + (z*5+1)*CC + lane);
    float we2 = __ldg(Wp + (z*5+2)*CC + lane);
    float we3 = __ldg(Wp + (z*5+3)*CC + lane);
    float we4 = __ldg(Wp + (z*5+4)*CC + lane);

    float vdot = v20*v20 + v21*v21 + v22*v22;
    float ps  = we0*s2 + we1*s2*s2 + we2*vdot;
    float pv0 = we3*v20 + we4*s2*v20;
    float pv1 = we3*v21 + we4*s2*v21;
    float pv2 = we3*v22 + we4*s2*v22;
    __syncwarp();
    xs[lane] = ps;
    xv[lane*3+0] = pv0; xv[lane*3+1] = pv1; xv[lane*3+2] = pv2;
    __syncwarp();

    float sn = scs, vn0 = sv0, vn1 = sv1, vn2 = sv2;
#pragma unroll
    for (int k = 0; k < CC; k++) {
        float wl = sWls[k*CC + lane], wlv = sWlv[k*CC + lane];
        sn  += xs[k]     * wl;
        vn0 += xv[k*3+0] * wlv;
        vn1 += xv[k*3+1] * wlv;
        vn2 += xv[k*3+2] * wlv;
    }
    g_sv[n*CC + lane] = make_float4(sn, vn0, vn1, vn2);
    out[n*(LL*CC) + l*CC + lane] = sn;
}

// ---------------- launch ------------------------------------------------------
extern "C" void kernel_launch(void* const* d_in, const int* in_sizes, int n_in,
                              void* d_out, int out_size) {
    const float* pos     = (const float*)d_in[0];
    const float* attrs   = (const float*)d_in[1];
    const float* shifts  = (const float*)d_in[2];
    const float* W_embed = (const float*)d_in[3];
    const float* W_up_s  = (const float*)d_in[4];
    const float* W_up_v  = (const float*)d_in[5];
    const float* R1      = (const float*)d_in[6];
    const float* R2      = (const float*)d_in[7];
    const float* R3      = (const float*)d_in[8];
    const float* W_out_s = (const float*)d_in[9];
    const float* W_out_v = (const float*)d_in[10];
    const float* Wsc_s   = (const float*)d_in[11];
    const float* Wsc_v   = (const float*)d_in[12];
    const float* Wp      = (const float*)d_in[13];
    const float* W_lin_s = (const float*)d_in[14];
    const float* W_lin_v = (const float*)d_in[15];
    const int*   ei      = (const int*)d_in[16];
    const int* src = ei;
    const int* dst = ei + EE;
    float* out = (float*)d_out;

    int smem = (NB*HH + HH*HH + 5*CC*KP + EW*HWF) * (int)sizeof(float); // 111104 B
    cudaFuncSetAttribute(k_edge, cudaFuncAttributeMaxDynamicSharedMemorySize, smem);

    k_zidx <<<(NN + 255)/256, 256>>>(attrs);
    k_embed<<<(NN*CC + 255)/256, 256>>>(W_embed);
    k_geom <<<(EE + 255)/256, 256>>>(pos, shifts, src, dst);

    for (int l = 0; l < LL; l++) {
        k_nodeup<<<(NN + NWU - 1)/NWU, NWU*32>>>(W_up_s + l*CC*CC, W_up_v + l*CC*CC);
        k_edge  <<<296, ETPB, smem>>>(R1 + l*NB*HH, R2 + l*HH*HH, R3 + l*HH*5*CC, src, dst);
        k_nodeupd<<<(NN + NWB - 1)/NWB, NWB*32>>>(
            W_out_s + l*CC*CC, W_out_v + l*CC*CC,
            Wsc_s + l*ZZ*CC*CC, Wsc_v + l*ZZ*CC*CC, Wp + l*ZZ*5*CC,
            W_lin_s + l*CC*CC, W_lin_v + l*CC*CC, out, l);
    }
}